// round 4
// baseline (speedup 1.0000x reference)
#include <cuda_runtime.h>
#include <math.h>

// ---------------- problem constants ----------------
#define NB    64
#define NPGc  50
#define EPGc  2048
#define NNODE (NB*NPGc)     // 3200
#define NEDGE (NB*EPGc)     // 131072
#define DLIN  1024
#define DCONV 12544
#define DREL  256
#define PP    50
#define KK    10
#define XX    100

#define CONV_SPLIT 16       // 12544/16 = 784 (mult of 16)
#define LIN_SPLIT  4        // 1024/4   = 256
#define NPARTS (CONV_SPLIT + LIN_SPLIT)
#define PARTSZ (NNODE*64)

// ---------------- scratch (static device mem; no allocs) ----------------
__device__ float g_node[NNODE*PP];
__device__ float g_parts[NPARTS*PARTSZ];
__device__ unsigned long long g_best[NB*PP];   // packed (enc(val)<<32 | (2047-e_local))
__device__ int   g_src[NEDGE];
__device__ int   g_dst[NEDGE];
__device__ float g_Lnode[PP];
__device__ float g_Lrel[PP];

// ---------------- helpers ----------------
__device__ __forceinline__ unsigned long long pk2(float x, float y) {
    unsigned long long r;
    asm("mov.b64 %0,{%1,%2};" : "=l"(r) : "f"(x), "f"(y));
    return r;
}
__device__ __forceinline__ void up2(unsigned long long v, float& a, float& b) {
    asm("mov.b64 {%0,%1},%2;" : "=f"(a), "=f"(b) : "l"(v));
}
__device__ __forceinline__ unsigned long long fma2(unsigned long long a,
                                                   unsigned long long b,
                                                   unsigned long long c) {
    unsigned long long d;
    asm("fma.rn.f32x2 %0,%1,%2,%3;" : "=l"(d) : "l"(a), "l"(b), "l"(c));
    return d;
}
// monotonic unsigned encoding of float
__device__ __forceinline__ unsigned fenc(float f) {
    unsigned u = __float_as_uint(f);
    return (u & 0x80000000u) ? ~u : (u | 0x80000000u);
}
__device__ __forceinline__ float fdec(unsigned u) {
    unsigned v = (u & 0x80000000u) ? (u ^ 0x80000000u) : ~u;
    return __uint_as_float(v);
}

// ---------------- kernel: normalize relation_indexes (int64 OR int32) + init ----------------
// Little-endian int64 values < 3200 -> every odd int32 word of the first row is 0.
// Genuine int32 data has random src values there (P(all 64 == 0) ~ 50^-64).
__global__ void normalize_ri_kernel(const int* __restrict__ RIw) {
    long long i = (long long)blockIdx.x * blockDim.x + threadIdx.x;
    bool is64 = true;
#pragma unroll
    for (int j = 0; j < 64; j++) is64 &= (RIw[2*j + 1] == 0);
    if (i < NEDGE) {
        if (is64) {
            g_src[i] = RIw[2*i];
            g_dst[i] = RIw[2*(NEDGE + i)];
        } else {
            g_src[i] = RIw[i];
            g_dst[i] = RIw[NEDGE + i];
        }
    }
    if (i < NB * PP) g_best[i] = 0ull;   // any real entry packs larger
}

// ---------------- kernel: L1 column norms ----------------
__global__ void l1_kernel(const float* __restrict__ Wobj,
                          const float* __restrict__ Wconv,
                          const float* __restrict__ Wrel) {
    int c = blockIdx.x;       // 0..49
    int t = threadIdx.x;      // 256 threads
    float sn = 0.f, sr = 0.f;
    for (int k = t; k < DLIN;  k += 256) sn += fabsf(Wobj [k*PP + c]);
    for (int k = t; k < DCONV; k += 256) sn += fabsf(Wconv[k*PP + c]);
    for (int k = t; k < DREL;  k += 256) sr += fabsf(Wrel [k*PP + c]);
    __shared__ float sh1[256], sh2[256];
    sh1[t] = sn; sh2[t] = sr;
    __syncthreads();
    for (int off = 128; off; off >>= 1) {
        if (t < off) { sh1[t] += sh1[t+off]; sh2[t] += sh2[t+off]; }
        __syncthreads();
    }
    if (t == 0) { g_Lnode[c] = sh1[0]; g_Lrel[c] = sh2[0]; }
}

// ---------------- kernel: node GEMM (split-K, conv+lin merged, reg-prefetch pipeline) ----------------
__global__ void __launch_bounds__(256)
node_gemm_kernel(const float* __restrict__ Aconv, const float* __restrict__ Wconv,
                 const float* __restrict__ Alin,  const float* __restrict__ Wlin) {
    int m0 = blockIdx.x * 64;
    const float* A; const float* W; int Kdim, kstart, kend;
    if (blockIdx.y < CONV_SPLIT) {
        A = Aconv; W = Wconv; Kdim = DCONV;
        kstart = blockIdx.y * (DCONV / CONV_SPLIT);
        kend = kstart + (DCONV / CONV_SPLIT);
    } else {
        A = Alin; W = Wlin; Kdim = DLIN;
        kstart = (blockIdx.y - CONV_SPLIT) * (DLIN / LIN_SPLIT);
        kend = kstart + (DLIN / LIN_SPLIT);
    }
    float* out = g_parts + (size_t)blockIdx.y * PARTSZ;

    __shared__ float As[16][68];
    __shared__ float Ws[16][64];
    int tid = threadIdx.x;
    int tx = tid & 15, ty = tid >> 4;

    unsigned long long acc[4][2];
#pragma unroll
    for (int i = 0; i < 4; i++) { acc[i][0] = pk2(0.f, 0.f); acc[i][1] = acc[i][0]; }

    int ar = tid >> 2, akq = tid & 3;
    int wk = tid >> 4, wn0 = (tid & 15) * 4;

    // prefetch first tile into registers
    float4 avr; float wvr0, wvr1, wvr2, wvr3;
    {
        int kt = kstart;
        avr = *(const float4*)&A[(size_t)(m0 + ar) * Kdim + kt + akq * 4];
        wvr0 = (wn0 + 0 < PP) ? W[(size_t)(kt + wk) * PP + wn0 + 0] : 0.f;
        wvr1 = (wn0 + 1 < PP) ? W[(size_t)(kt + wk) * PP + wn0 + 1] : 0.f;
        wvr2 = (wn0 + 2 < PP) ? W[(size_t)(kt + wk) * PP + wn0 + 2] : 0.f;
        wvr3 = (wn0 + 3 < PP) ? W[(size_t)(kt + wk) * PP + wn0 + 3] : 0.f;
    }

    for (int kt = kstart; kt < kend; kt += 16) {
        As[akq*4+0][ar] = avr.x; As[akq*4+1][ar] = avr.y;
        As[akq*4+2][ar] = avr.z; As[akq*4+3][ar] = avr.w;
        Ws[wk][wn0+0] = wvr0; Ws[wk][wn0+1] = wvr1;
        Ws[wk][wn0+2] = wvr2; Ws[wk][wn0+3] = wvr3;
        __syncthreads();

        int ktn = kt + 16;
        if (ktn < kend) {    // prefetch next tile while computing on this one
            avr = *(const float4*)&A[(size_t)(m0 + ar) * Kdim + ktn + akq * 4];
            wvr0 = (wn0 + 0 < PP) ? W[(size_t)(ktn + wk) * PP + wn0 + 0] : 0.f;
            wvr1 = (wn0 + 1 < PP) ? W[(size_t)(ktn + wk) * PP + wn0 + 1] : 0.f;
            wvr2 = (wn0 + 2 < PP) ? W[(size_t)(ktn + wk) * PP + wn0 + 2] : 0.f;
            wvr3 = (wn0 + 3 < PP) ? W[(size_t)(ktn + wk) * PP + wn0 + 3] : 0.f;
        }

#pragma unroll
        for (int kk = 0; kk < 16; kk++) {
            float4 a = *(const float4*)&As[kk][ty*4];
            const unsigned long long* wr = (const unsigned long long*)&Ws[kk][tx*4];
            unsigned long long w01 = wr[0], w23 = wr[1];
            unsigned long long a0 = pk2(a.x, a.x), a1 = pk2(a.y, a.y);
            unsigned long long a2 = pk2(a.z, a.z), a3 = pk2(a.w, a.w);
            acc[0][0] = fma2(a0, w01, acc[0][0]); acc[0][1] = fma2(a0, w23, acc[0][1]);
            acc[1][0] = fma2(a1, w01, acc[1][0]); acc[1][1] = fma2(a1, w23, acc[1][1]);
            acc[2][0] = fma2(a2, w01, acc[2][0]); acc[2][1] = fma2(a2, w23, acc[2][1]);
            acc[3][0] = fma2(a3, w01, acc[3][0]); acc[3][1] = fma2(a3, w23, acc[3][1]);
        }
        __syncthreads();
    }
#pragma unroll
    for (int i = 0; i < 4; i++) {
        float4 v;
        up2(acc[i][0], v.x, v.y);
        up2(acc[i][1], v.z, v.w);
        *(float4*)&out[(size_t)(m0 + ty*4 + i) * 64 + tx*4] = v;
    }
}

// ---------------- kernel: reduce partials into node[N][50] ----------------
__global__ void reduce_node_kernel() {
    int idx = blockIdx.x * blockDim.x + threadIdx.x;
    if (idx >= NNODE * PP) return;
    int n = idx / PP, c = idx % PP;
    float s = 0.f;
#pragma unroll
    for (int p = 0; p < NPARTS; p++) s += g_parts[(size_t)p * PARTSZ + n*64 + c];
    g_node[idx] = s;
}

// ---------------- kernel: rel GEMM + gather + per-(b,class) arg/max ----------------
__global__ void __launch_bounds__(256)
rel_edge_kernel(const float* __restrict__ A,          // rel_lin [E,256]
                const float* __restrict__ W) {        // W_rel [256,50]
    int m0 = blockIdx.x * 64;
    int b = m0 / EPGc;
    int e0 = m0 - b * EPGc;        // local edge base within batch

    __shared__ float As[16][68];
    __shared__ float Ws[16][64];
    __shared__ float ns[64][52];
    __shared__ float smx[16][64];
    __shared__ int   six[16][64];

    int tid = threadIdx.x;
    int tx = tid & 15, ty = tid >> 4;

    unsigned long long acc[4][2];
#pragma unroll
    for (int i = 0; i < 4; i++) { acc[i][0] = pk2(0.f, 0.f); acc[i][1] = acc[i][0]; }

    int ar = tid >> 2, akq = tid & 3;
    int wk = tid >> 4, wn0 = (tid & 15) * 4;

    // prefetch first tile
    float4 avr; float wvr0, wvr1, wvr2, wvr3;
    avr = *(const float4*)&A[(size_t)(m0 + ar) * DREL + akq * 4];
    wvr0 = (wn0 + 0 < PP) ? W[(size_t)wk * PP + wn0 + 0] : 0.f;
    wvr1 = (wn0 + 1 < PP) ? W[(size_t)wk * PP + wn0 + 1] : 0.f;
    wvr2 = (wn0 + 2 < PP) ? W[(size_t)wk * PP + wn0 + 2] : 0.f;
    wvr3 = (wn0 + 3 < PP) ? W[(size_t)wk * PP + wn0 + 3] : 0.f;

    for (int kt = 0; kt < DREL; kt += 16) {
        As[akq*4+0][ar] = avr.x; As[akq*4+1][ar] = avr.y;
        As[akq*4+2][ar] = avr.z; As[akq*4+3][ar] = avr.w;
        Ws[wk][wn0+0] = wvr0; Ws[wk][wn0+1] = wvr1;
        Ws[wk][wn0+2] = wvr2; Ws[wk][wn0+3] = wvr3;
        __syncthreads();

        int ktn = kt + 16;
        if (ktn < DREL) {
            avr = *(const float4*)&A[(size_t)(m0 + ar) * DREL + ktn + akq * 4];
            wvr0 = (wn0 + 0 < PP) ? W[(size_t)(ktn + wk) * PP + wn0 + 0] : 0.f;
            wvr1 = (wn0 + 1 < PP) ? W[(size_t)(ktn + wk) * PP + wn0 + 1] : 0.f;
            wvr2 = (wn0 + 2 < PP) ? W[(size_t)(ktn + wk) * PP + wn0 + 2] : 0.f;
            wvr3 = (wn0 + 3 < PP) ? W[(size_t)(ktn + wk) * PP + wn0 + 3] : 0.f;
        }

#pragma unroll
        for (int kk = 0; kk < 16; kk++) {
            float4 a = *(const float4*)&As[kk][ty*4];
            const unsigned long long* wr = (const unsigned long long*)&Ws[kk][tx*4];
            unsigned long long w01 = wr[0], w23 = wr[1];
            unsigned long long a0 = pk2(a.x, a.x), a1 = pk2(a.y, a.y);
            unsigned long long a2 = pk2(a.z, a.z), a3 = pk2(a.w, a.w);
            acc[0][0] = fma2(a0, w01, acc[0][0]); acc[0][1] = fma2(a0, w23, acc[0][1]);
            acc[1][0] = fma2(a1, w01, acc[1][0]); acc[1][1] = fma2(a1, w23, acc[1][1]);
            acc[2][0] = fma2(a2, w01, acc[2][0]); acc[2][1] = fma2(a2, w23, acc[2][1]);
            acc[3][0] = fma2(a3, w01, acc[3][0]); acc[3][1] = fma2(a3, w23, acc[3][1]);
        }
        __syncthreads();
    }

    // gather node[src]+node[dst] for this block's 64 edges
    {
        int r = tid >> 2, q = tid & 3;
        int e = m0 + r;
        int s = g_src[e];
        int d = g_dst[e];
        for (int c = q; c < PP; c += 4)
            ns[r][c] = g_node[s*PP + c] + g_node[d*PP + c];
    }
    __syncthreads();

    float col[4][4];
#pragma unroll
    for (int i = 0; i < 4; i++) {
        up2(acc[i][0], col[i][0], col[i][1]);
        up2(acc[i][1], col[i][2], col[i][3]);
    }

    // per-thread max+argmax over its 4 rows per class (strict > => lowest idx wins)
#pragma unroll
    for (int j = 0; j < 4; j++) {
        int c = tx*4 + j;
        float bv = -3.4e38f; int bi = 0;
        if (c < PP) {
#pragma unroll
            for (int i = 0; i < 4; i++) {
                float t = col[i][j] + ns[ty*4+i][c];
                if (t > bv) { bv = t; bi = ty*4 + i; }
            }
        }
        smx[ty][c] = bv;
        six[ty][c] = bi;
    }
    __syncthreads();
    if (ty == 0) {
#pragma unroll
        for (int j = 0; j < 4; j++) {
            int c = tx*4 + j;
            if (c < PP) {
                float bv = smx[0][c]; int bi = six[0][c];
#pragma unroll
                for (int r = 1; r < 16; r++) {
                    if (smx[r][c] > bv) { bv = smx[r][c]; bi = six[r][c]; }
                }
                unsigned long long pkd =
                    ((unsigned long long)fenc(bv) << 32) |
                    (unsigned long long)(unsigned)(EPGc - 1 - (e0 + bi));
                atomicMax(&g_best[b*PP + c], pkd);
            }
        }
    }
}

// ---------------- kernel: topk + score + top-100 assembly ----------------
__global__ void finalize_kernel(float* __restrict__ out) {
    int b = threadIdx.x;
    if (b >= NB) return;

    float pr[PP];
    int   am[PP];
    for (int c = 0; c < PP; c++) {
        unsigned long long pkd = g_best[b*PP + c];
        float l = fdec((unsigned)(pkd >> 32));
        pr[c] = 1.f / (1.f + expf(-l));
        am[c] = EPGc - 1 - (int)(pkd & 0xFFFFFFFFull);
    }
    float scoreK[KK]; int classK[KK]; int argmK[KK];
    for (int k = 0; k < KK; k++) {
        float bv = -1.f; int bc = 0;
        for (int c = 0; c < PP; c++)
            if (pr[c] > bv) { bv = pr[c]; bc = c; }
        scoreK[k] = bv; classK[k] = bc; argmK[k] = am[bc];
        pr[bc] = -1.f;
    }

    float vals[KK];
    int   fidx[KK];
    for (int k = 0; k < KK; k++) {
        int c = classK[k];
        float s = scoreK[k];
        int el = argmK[k];
        int eg = b * EPGc + el;
        int sN = g_src[eg], dN = g_dst[eg];
        float g = s * (1.f - s);
        float Ln = g_Lnode[c], Lr = g_Lrel[c];
        float m = (sN == dN) ? 4.f : 1.f;
        vals[k] = g * g * g * s * m * Ln * Ln * Lr;
        fidx[k] = el * KK + k;
    }
    // sort 10 desc by value (tie: lower flat index first)
    int ord[KK];
    for (int k = 0; k < KK; k++) ord[k] = k;
    for (int i = 0; i < KK; i++)
        for (int j = i + 1; j < KK; j++) {
            int a = ord[i], bb = ord[j];
            if (vals[bb] > vals[a] || (vals[bb] == vals[a] && fidx[bb] < fidx[a])) {
                ord[i] = bb; ord[j] = a;
            }
        }

    auto emit = [&](int pos, float v, int f) {
        int r = b * XX + pos;
        int el = f / KK, kq = f % KK;
        int eg = b * EPGc + el;
        out[r]          = v;
        out[6400  + r]  = (float)g_src[eg];
        out[12800 + r]  = (float)g_dst[eg];
        out[19200 + r]  = scoreK[kq];
        out[25600 + r]  = (float)classK[kq];
    };

    for (int pos = 0; pos < KK; pos++) {
        int k = ord[pos];
        emit(pos, vals[k], fidx[k]);
    }
    // 90 lowest-flat-index zeros (stable top_k over equal values)
    int pos = KK, idx = 0;
    while (pos < XX) {
        bool used = false;
        for (int k = 0; k < KK; k++) if (fidx[k] == idx) used = true;
        if (!used) { emit(pos, 0.f, idx); pos++; }
        idx++;
    }
    out[32000 + b] = (float)XX;   // n_relations
}

// ---------------- launch ----------------
extern "C" void kernel_launch(void* const* d_in, const int* in_sizes, int n_in,
                              void* d_out, int out_size) {
    const float *obj_lin = 0, *obj_conv = 0, *rel_lin = 0, *Wobj = 0, *Wconv = 0, *Wrel = 0;
    const void* RI = 0;
    for (int i = 0; i < n_in; i++) {
        switch (in_sizes[i]) {
            case 3276800:  obj_lin  = (const float*)d_in[i]; break;
            case 40140800: obj_conv = (const float*)d_in[i]; break;
            case 33554432: rel_lin  = (const float*)d_in[i]; break;
            case 262144:   RI       = d_in[i]; break;
            case 51200:    Wobj     = (const float*)d_in[i]; break;
            case 627200:   Wconv    = (const float*)d_in[i]; break;
            case 12800:    Wrel     = (const float*)d_in[i]; break;
            default: break;
        }
    }
    if (!obj_lin || !obj_conv || !rel_lin || !RI || !Wobj || !Wconv || !Wrel) {
        obj_lin  = (const float*)d_in[0];
        obj_conv = (const float*)d_in[1];
        rel_lin  = (const float*)d_in[2];
        RI       = d_in[3];
        Wobj     = (const float*)d_in[4];
        Wconv    = (const float*)d_in[5];
        Wrel     = (const float*)d_in[6];
    }
    float* out = (float*)d_out;

    normalize_ri_kernel<<<(NEDGE + 255)/256, 256>>>((const int*)RI);
    l1_kernel<<<PP, 256>>>(Wobj, Wconv, Wrel);
    node_gemm_kernel<<<dim3(NNODE/64, NPARTS), 256>>>(obj_conv, Wconv, obj_lin, Wobj);
    reduce_node_kernel<<<(NNODE*PP + 255)/256, 256>>>();
    rel_edge_kernel<<<NEDGE/64, 256>>>(rel_lin, Wrel);
    finalize_kernel<<<1, 64>>>(out);
}